// round 14
// baseline (speedup 1.0000x reference)
#include <cuda_runtime.h>
#include <cuda_bf16.h>
#include <cstdint>

#define NN 100000
#define EE 1200000

// Scratch: aggregated messages per node [N, 64]; zero at entry, MLP re-zeroes.
__device__ float g_agg[NN * 64];
// Pre-transposed hi/lo-split weights in smem-tile layout (filled per launch).
__device__ __nv_bfloat16 g_w1s[128 * 136];   // [j][k] hi @k, lo @k+64
__device__ __nv_bfloat16 g_w2s[64 * 264];    // [j][k] hi @k, lo @k+128

// ---------------------------------------------------------------------------
// Kernel 1: scatter-add (best measured variant: 16 threads/edge, RED.v4)
// ---------------------------------------------------------------------------
__global__ void scatter_kernel(const float* __restrict__ node_feat,
                               const float* __restrict__ edge_feat,
                               const int* __restrict__ ei, int E) {
    int gid = blockIdx.x * blockDim.x + threadIdx.x;
    if (gid >= E * 16) return;
    int e = gid >> 4;
    int c = gid & 15;
    int s = __ldg(ei + e);
    int d = __ldg(ei + E + e);
    float4 nf = __ldg(((const float4*)node_feat) + s * 16 + c);
    float4 ef = __ldg(((const float4*)edge_feat) + (size_t)e * 16 + c);
    float4 m = make_float4(nf.x + ef.x, nf.y + ef.y, nf.z + ef.z, nf.w + ef.w);
    float* p = g_agg + (size_t)d * 64 + (c << 2);
    asm volatile("red.global.add.v4.f32 [%0], {%1, %2, %3, %4};"
                 :: "l"(p), "f"(m.x), "f"(m.y), "f"(m.z), "f"(m.w)
                 : "memory");
}

// ---------------------------------------------------------------------------
// Helpers
// ---------------------------------------------------------------------------
__device__ __forceinline__ uint32_t smem_u32(const void* p) {
    uint32_t a;
    asm("{ .reg .u64 t; cvta.to.shared.u64 t, %1; cvt.u32.u64 %0, t; }"
        : "=r"(a) : "l"(p));
    return a;
}

#define LDMX4(d0, d1, d2, d3, addr) \
    asm volatile("ldmatrix.sync.aligned.m8n8.x4.shared.b16 {%0,%1,%2,%3}, [%4];" \
                 : "=r"(d0), "=r"(d1), "=r"(d2), "=r"(d3) : "r"(addr))

#define MMA16816(c, a0, a1, a2, a3, b0, b1) \
    asm volatile("mma.sync.aligned.m16n8k16.row.col.f32.bf16.bf16.f32 " \
                 "{%0,%1,%2,%3}, {%4,%5,%6,%7}, {%8,%9}, {%0,%1,%2,%3};" \
                 : "+f"((c)[0]), "+f"((c)[1]), "+f"((c)[2]), "+f"((c)[3]) \
                 : "r"(a0), "r"(a1), "r"(a2), "r"(a3), "r"(b0), "r"(b1))

__device__ __forceinline__ uint32_t pack_bf2(float x, float y) {
    return (uint32_t)__bfloat16_as_ushort(__float2bfloat16(x)) |
           ((uint32_t)__bfloat16_as_ushort(__float2bfloat16(y)) << 16);
}
__device__ __forceinline__ float bf_hi(float x) {
    return __bfloat162float(__float2bfloat16(x));
}

// Store 4 values as hi-pair (v2.b32 at k) + lo-pair (v2.b32 at k+lo_off).
__device__ __forceinline__ void st_hilo4(uint32_t base, int stride, int row,
                                         int k, int lo_off, float4 v) {
    float h0 = bf_hi(v.x), h1 = bf_hi(v.y), h2 = bf_hi(v.z), h3 = bf_hi(v.w);
    uint32_t hw0 = pack_bf2(v.x, v.y), hw1 = pack_bf2(v.z, v.w);
    uint32_t lw0 = pack_bf2(v.x - h0, v.y - h1), lw1 = pack_bf2(v.z - h2, v.w - h3);
    uint32_t a0 = base + (uint32_t)((row * stride + k) * 2);
    asm volatile("st.shared.v2.b32 [%0], {%1, %2};" :: "r"(a0), "r"(hw0), "r"(hw1));
    asm volatile("st.shared.v2.b32 [%0], {%1, %2};"
                 :: "r"(a0 + (uint32_t)(lo_off * 2)), "r"(lw0), "r"(lw1));
}

// hi/lo split store into a global bf16 buffer (prep kernel)
__device__ __forceinline__ void g_hilo(__nv_bfloat16* base, int stride, int row,
                                       int k, int lo_off, float x0, float x1) {
    __nv_bfloat16 h0 = __float2bfloat16(x0), h1 = __float2bfloat16(x1);
    base[row * stride + k]     = h0;
    base[row * stride + k + 1] = h1;
    base[row * stride + k + lo_off]     = __float2bfloat16(x0 - __bfloat162float(h0));
    base[row * stride + k + lo_off + 1] = __float2bfloat16(x1 - __bfloat162float(h1));
}

// ---------------------------------------------------------------------------
// Kernel 0: per-launch weight transpose + hi/lo split into global buffers.
// ---------------------------------------------------------------------------
__global__ void prep_w_kernel(const float* __restrict__ W1,
                              const float* __restrict__ W2) {
    int q = blockIdx.x * 256 + threadIdx.x;    // 0..2047
    if (q < 1024) {
        int kp = q & 31, j4 = q >> 5;
        int k0 = kp * 2;
        float4 wa = __ldg(((const float4*)W1) + k0 * 32 + j4);
        float4 wb = __ldg(((const float4*)W1) + (k0 + 1) * 32 + j4);
        int j = j4 * 4;
        g_hilo(g_w1s, 136, j + 0, k0, 64, wa.x, wb.x);
        g_hilo(g_w1s, 136, j + 1, k0, 64, wa.y, wb.y);
        g_hilo(g_w1s, 136, j + 2, k0, 64, wa.z, wb.z);
        g_hilo(g_w1s, 136, j + 3, k0, 64, wa.w, wb.w);
    } else {
        q -= 1024;
        int kp = q & 63, j4 = q >> 6;
        int k0 = kp * 2;
        float4 wa = __ldg(((const float4*)W2) + k0 * 16 + j4);
        float4 wb = __ldg(((const float4*)W2) + (k0 + 1) * 16 + j4);
        int j = j4 * 4;
        g_hilo(g_w2s, 264, j + 0, k0, 128, wa.x, wb.x);
        g_hilo(g_w2s, 264, j + 1, k0, 128, wa.y, wb.y);
        g_hilo(g_w2s, 264, j + 2, k0, 128, wa.z, wb.z);
        g_hilo(g_w2s, 264, j + 3, k0, 128, wa.w, wb.w);
    }
}

// ---------------------------------------------------------------------------
// Kernel 2: HMMA MLP, H kept in registers. 128 nodes/block, 256 threads.
// Warp w owns rows [w*16, w*16+16): GEMM1 16m x 128j; in-register
// bias+relu+hi/lo conversion (C-fragment == A-fragment layout);
// GEMM2 16m x 64j over k = 256 (Hhi|Hlo). No inter-GEMM smem or barriers.
//   Abuf  [128m][136] bf16: Ahi | Alo        @ 0      (34816B)
//   W1buf [128j][136] bf16 (from g_w1s)      @ 34816  (34816B)
//   W2buf [64j][264]  bf16 (from g_w2s)      @ 69632  (33792B)
// ---------------------------------------------------------------------------
#define MLP_THREADS 256
#define AS 136
#define HS 264
#define OFF_A  0u
#define OFF_W1 34816u
#define OFF_W2 69632u
#define SMEM_TOTAL 103424

__global__ void __launch_bounds__(MLP_THREADS, 2) mlp_mma_kernel(
    const float* __restrict__ b1, const float* __restrict__ b2,
    float* __restrict__ out, int N) {
    extern __shared__ char smc[];
    uint32_t sb = smem_u32(smc);
    int tid = threadIdx.x;
    int lane = tid & 31;
    int wid = tid >> 5;
    int node0 = blockIdx.x * 128;

    // ---- stage weights: linear 16B memcpy from pre-split global buffers ----
    {
        const uint4* w1g = (const uint4*)g_w1s;
        uint4* w1smem = (uint4*)(smc + OFF_W1);
#pragma unroll
        for (int i = 0; i < 9; i++) {
            int f = tid + i * 256;
            if (f < 2176) w1smem[f] = __ldg(w1g + f);
        }
        const uint4* w2g = (const uint4*)g_w2s;
        uint4* w2smem = (uint4*)(smc + OFF_W2);
#pragma unroll
        for (int i = 0; i < 9; i++) {
            int f = tid + i * 256;
            if (f < 2112) w2smem[f] = __ldg(w2g + f);
        }
    }
    // ---- stage A (hi|lo) from g_agg; re-zero g_agg ----
#pragma unroll
    for (int i = 0; i < 8; i++) {
        int f = tid + i * 256;
        int r = f >> 4, c4 = f & 15;
        int n = node0 + r;
        float4 v = make_float4(0.f, 0.f, 0.f, 0.f);
        if (n < N) {
            v = __ldg(((const float4*)g_agg) + (size_t)n * 16 + c4);
            ((float4*)g_agg)[(size_t)n * 16 + c4] = make_float4(0.f, 0.f, 0.f, 0.f);
        }
        st_hilo4(sb + OFF_A, AS, r, c4 * 4, 64, v);
    }
    __syncthreads();

    // Fragment lane offsets (PTX m16n8k16 canonical mappings)
    int rA = (lane & 7) + ((lane >> 3) & 1) * 8;
    int cA = (lane >> 4) * 8;
    int rB = (lane & 7) + (lane >> 4) * 8;
    int cB = ((lane >> 3) & 1) * 8;
    int m0 = wid * 16;
    int g = lane >> 2;
    int cpair = (lane & 3) * 2;

    // ---------------- GEMM1: D1 = Ahi·Whi + Ahi·Wlo + Alo·Whi (16m x 128j) ----
    float acc[16][4];
#pragma unroll
    for (int q = 0; q < 16; q++)
#pragma unroll
        for (int p = 0; p < 4; p++) acc[q][p] = 0.f;

#pragma unroll 4
    for (int s = 0; s < 12; s++) {
        int ka = ((s & 3) << 4) + ((s >= 8) ? 64 : 0);
        int kb = ((s & 3) << 4) + ((s >= 4 && s < 8) ? 64 : 0);
        uint32_t a0, a1, a2, a3;
        LDMX4(a0, a1, a2, a3, sb + OFF_A + (uint32_t)(((m0 + rA) * AS + ka + cA) * 2));
#pragma unroll
        for (int nt = 0; nt < 8; nt++) {
            uint32_t b0, b1r, b2, b3;
            LDMX4(b0, b1r, b2, b3,
                  sb + OFF_W1 + (uint32_t)(((nt * 16 + rB) * AS + kb + cB) * 2));
            MMA16816(acc[2 * nt],     a0, a1, a2, a3, b0, b1r);
            MMA16816(acc[2 * nt + 1], a0, a1, a2, a3, b2, b3);
        }
    }

    // ---- in-register epilogue 1: +b1, relu, hi/lo split -> A-fragments ----
    // C-fragment of tile q (cols q*8..q*8+7) maps to A-fragment of kstep s=q/2:
    //   a0 <- (c0,c1) of tile 2s; a1 <- (c2,c3) of tile 2s;
    //   a2 <- (c0,c1) of tile 2s+1; a3 <- (c2,c3) of tile 2s+1.
    uint32_t ah[8][4], al[8][4];
#pragma unroll
    for (int s = 0; s < 8; s++) {
#pragma unroll
        for (int half = 0; half < 2; half++) {
            int q = 2 * s + half;
            int c0 = q * 8 + cpair;
            float bv0 = __ldg(b1 + c0), bv1 = __ldg(b1 + c0 + 1);
            float x0 = fmaxf(acc[q][0] + bv0, 0.f);
            float x1 = fmaxf(acc[q][1] + bv1, 0.f);
            float x2 = fmaxf(acc[q][2] + bv0, 0.f);
            float x3 = fmaxf(acc[q][3] + bv1, 0.f);
            ah[s][2 * half]     = pack_bf2(x0, x1);
            ah[s][2 * half + 1] = pack_bf2(x2, x3);
            al[s][2 * half]     = pack_bf2(x0 - bf_hi(x0), x1 - bf_hi(x1));
            al[s][2 * half + 1] = pack_bf2(x2 - bf_hi(x2), x3 - bf_hi(x3));
        }
    }

    // ---------------- GEMM2: D2 = Hhi·W2hi + Hlo·W2hi + Hhi·W2lo (16m x 64j) --
    float acc2[8][4];
#pragma unroll
    for (int q = 0; q < 8; q++)
#pragma unroll
        for (int p = 0; p < 4; p++) acc2[q][p] = 0.f;

#pragma unroll
    for (int s = 0; s < 24; s++) {
        int ks = s & 7;
        int kw = ks * 16 + ((s >= 16) ? 128 : 0);
        const uint32_t* af = (s >= 8 && s < 16) ? al[ks] : ah[ks];
#pragma unroll
        for (int nt = 0; nt < 4; nt++) {
            uint32_t b0, b1r, b2, b3;
            LDMX4(b0, b1r, b2, b3,
                  sb + OFF_W2 + (uint32_t)(((nt * 16 + rB) * HS + kw + cB) * 2));
            MMA16816(acc2[2 * nt],     af[0], af[1], af[2], af[3], b0, b1r);
            MMA16816(acc2[2 * nt + 1], af[0], af[1], af[2], af[3], b2, b3);
        }
    }

    // ---- epilogue 2: +b2 -> out ----
    {
        int n0r = node0 + m0 + g;
        int n1r = n0r + 8;
#pragma unroll
        for (int q = 0; q < 8; q++) {
            int c0 = q * 8 + cpair;
            float bv0 = __ldg(b2 + c0), bv1 = __ldg(b2 + c0 + 1);
            if (n0r < N)
                *(float2*)(out + (size_t)n0r * 64 + c0) =
                    make_float2(acc2[q][0] + bv0, acc2[q][1] + bv1);
            if (n1r < N)
                *(float2*)(out + (size_t)n1r * 64 + c0) =
                    make_float2(acc2[q][2] + bv0, acc2[q][3] + bv1);
        }
    }
}

// ---------------------------------------------------------------------------
// Launch: prep weights -> scatter -> HMMA MLP
// ---------------------------------------------------------------------------
extern "C" void kernel_launch(void* const* d_in, const int* in_sizes, int n_in,
                              void* d_out, int out_size) {
    const float* node_feat = (const float*)d_in[0];
    const float* edge_feat = (const float*)d_in[1];
    const int*   ei        = (const int*)d_in[2];
    const float* W1        = (const float*)d_in[3];
    const float* b1        = (const float*)d_in[4];
    const float* W2        = (const float*)d_in[5];
    const float* b2        = (const float*)d_in[6];
    float* out = (float*)d_out;

    int N = in_sizes[0] / 64;   // 100000
    int E = in_sizes[2] / 2;    // 1200000

    cudaFuncSetAttribute(mlp_mma_kernel, cudaFuncAttributeMaxDynamicSharedMemorySize,
                         SMEM_TOTAL);

    prep_w_kernel<<<8, 256>>>(W1, W2);
    scatter_kernel<<<(E * 16 + 255) / 256, 256>>>(node_feat, edge_feat, ei, E);
    mlp_mma_kernel<<<(N + 127) / 128, MLP_THREADS, SMEM_TOTAL>>>(b1, b2, out, N);
}

// round 15
// speedup vs baseline: 1.1459x; 1.1459x over previous
#include <cuda_runtime.h>
#include <cuda_bf16.h>
#include <cstdint>

#define NN 100000
#define EE 1200000

// Scratch: aggregated messages per node [N, 64]; zero at entry, MLP re-zeroes.
__device__ float g_agg[NN * 64];
// Pre-transposed hi/lo-split weights in smem-tile layout (filled per launch
// by the first 8 blocks of scatter_kernel).
__device__ __nv_bfloat16 g_w1s[128 * 136];   // [j][k] hi @k, lo @k+64
__device__ __nv_bfloat16 g_w2s[64 * 264];    // [j][k] hi @k, lo @k+128

// ---------------------------------------------------------------------------
// Helpers
// ---------------------------------------------------------------------------
__device__ __forceinline__ uint32_t smem_u32(const void* p) {
    uint32_t a;
    asm("{ .reg .u64 t; cvta.to.shared.u64 t, %1; cvt.u32.u64 %0, t; }"
        : "=r"(a) : "l"(p));
    return a;
}

#define LDMX4(d0, d1, d2, d3, addr) \
    asm volatile("ldmatrix.sync.aligned.m8n8.x4.shared.b16 {%0,%1,%2,%3}, [%4];" \
                 : "=r"(d0), "=r"(d1), "=r"(d2), "=r"(d3) : "r"(addr))

#define MMA16816(c, a0, a1, a2, a3, b0, b1) \
    asm volatile("mma.sync.aligned.m16n8k16.row.col.f32.bf16.bf16.f32 " \
                 "{%0,%1,%2,%3}, {%4,%5,%6,%7}, {%8,%9}, {%0,%1,%2,%3};" \
                 : "+f"((c)[0]), "+f"((c)[1]), "+f"((c)[2]), "+f"((c)[3]) \
                 : "r"(a0), "r"(a1), "r"(a2), "r"(a3), "r"(b0), "r"(b1))

// hi/lo split store into shared memory (used for A and H staging)
__device__ __forceinline__ void st_hilo2(uint32_t base, int stride, int row,
                                         int k, int lo_off, float x0, float x1) {
    __nv_bfloat16 h0 = __float2bfloat16(x0), h1 = __float2bfloat16(x1);
    __nv_bfloat16 g0 = __float2bfloat16(x0 - __bfloat162float(h0));
    __nv_bfloat16 g1 = __float2bfloat16(x1 - __bfloat162float(h1));
    uint32_t hw = (uint32_t)__bfloat16_as_ushort(h0) |
                  ((uint32_t)__bfloat16_as_ushort(h1) << 16);
    uint32_t lw = (uint32_t)__bfloat16_as_ushort(g0) |
                  ((uint32_t)__bfloat16_as_ushort(g1) << 16);
    uint32_t a0 = base + (uint32_t)((row * stride + k) * 2);
    uint32_t a1 = base + (uint32_t)((row * stride + k + lo_off) * 2);
    asm volatile("st.shared.b32 [%0], %1;" :: "r"(a0), "r"(hw));
    asm volatile("st.shared.b32 [%0], %1;" :: "r"(a1), "r"(lw));
}

// hi/lo split store into a global bf16 buffer (prep path)
__device__ __forceinline__ void g_hilo(__nv_bfloat16* base, int stride, int row,
                                       int k, int lo_off, float x0, float x1) {
    __nv_bfloat16 h0 = __float2bfloat16(x0), h1 = __float2bfloat16(x1);
    base[row * stride + k]     = h0;
    base[row * stride + k + 1] = h1;
    base[row * stride + k + lo_off]     = __float2bfloat16(x0 - __bfloat162float(h0));
    base[row * stride + k + lo_off + 1] = __float2bfloat16(x1 - __bfloat162float(h1));
}

// ---------------------------------------------------------------------------
// Kernel 1: scatter-add (16 threads/edge, RED.v4). Blocks 0-7 additionally
// perform the per-launch weight transpose + hi/lo split (hidden under the
// scatter's memory-bound runtime; saves a serial prep launch).
// ---------------------------------------------------------------------------
__global__ void scatter_kernel(const float* __restrict__ node_feat,
                               const float* __restrict__ edge_feat,
                               const int* __restrict__ ei, int E,
                               const float* __restrict__ W1,
                               const float* __restrict__ W2) {
    if (blockIdx.x < 8) {
        int q = blockIdx.x * 256 + threadIdx.x;    // 0..2047
        if (q < 1024) {
            int kp = q & 31, j4 = q >> 5;
            int k0 = kp * 2;
            float4 wa = __ldg(((const float4*)W1) + k0 * 32 + j4);
            float4 wb = __ldg(((const float4*)W1) + (k0 + 1) * 32 + j4);
            int j = j4 * 4;
            g_hilo(g_w1s, 136, j + 0, k0, 64, wa.x, wb.x);
            g_hilo(g_w1s, 136, j + 1, k0, 64, wa.y, wb.y);
            g_hilo(g_w1s, 136, j + 2, k0, 64, wa.z, wb.z);
            g_hilo(g_w1s, 136, j + 3, k0, 64, wa.w, wb.w);
        } else {
            int q2 = q - 1024;
            int kp = q2 & 63, j4 = q2 >> 6;
            int k0 = kp * 2;
            float4 wa = __ldg(((const float4*)W2) + k0 * 16 + j4);
            float4 wb = __ldg(((const float4*)W2) + (k0 + 1) * 16 + j4);
            int j = j4 * 4;
            g_hilo(g_w2s, 264, j + 0, k0, 128, wa.x, wb.x);
            g_hilo(g_w2s, 264, j + 1, k0, 128, wa.y, wb.y);
            g_hilo(g_w2s, 264, j + 2, k0, 128, wa.z, wb.z);
            g_hilo(g_w2s, 264, j + 3, k0, 128, wa.w, wb.w);
        }
    }
    int gid = blockIdx.x * blockDim.x + threadIdx.x;
    if (gid >= E * 16) return;
    int e = gid >> 4;
    int c = gid & 15;
    int s = __ldg(ei + e);
    int d = __ldg(ei + E + e);
    float4 nf = __ldg(((const float4*)node_feat) + s * 16 + c);
    float4 ef = __ldg(((const float4*)edge_feat) + (size_t)e * 16 + c);
    float4 m = make_float4(nf.x + ef.x, nf.y + ef.y, nf.z + ef.z, nf.w + ef.w);
    float* p = g_agg + (size_t)d * 64 + (c << 2);
    asm volatile("red.global.add.v4.f32 [%0], {%1, %2, %3, %4};"
                 :: "l"(p), "f"(m.x), "f"(m.y), "f"(m.z), "f"(m.w)
                 : "memory");
}

// ---------------------------------------------------------------------------
// Kernel 2: HMMA MLP (round-13 best). 128 nodes/block, 256 threads
// (4m x 2j warp grid), 2 blocks/SM.
//   Abuf  [128m][136] bf16: Ahi | Alo                 @ 0      (34816B)
//   W1buf [128j][136] bf16 (memcpy from g_w1s)        @ 34816  (34816B)
//   Hbuf  [128m][264] bf16: Hhi | Hlo                 @ 0      (aliases A+W1)
//   W2buf [64j][264]  bf16 (memcpy from g_w2s)        @ 69632  (33792B)
// Warp tiles: GEMM1 32m x 64j; GEMM2 32m x 32j.
// ---------------------------------------------------------------------------
#define MLP_THREADS 256
#define AS 136
#define HS 264
#define OFF_A  0u
#define OFF_W1 34816u
#define OFF_W2 69632u
#define SMEM_TOTAL 103424

__global__ void __launch_bounds__(MLP_THREADS, 2) mlp_mma_kernel(
    const float* __restrict__ b1, const float* __restrict__ b2,
    float* __restrict__ out, int N) {
    extern __shared__ char smc[];
    uint32_t sb = smem_u32(smc);
    int tid = threadIdx.x;
    int lane = tid & 31;
    int wid = tid >> 5;
    int node0 = blockIdx.x * 128;

    // ---- stage weights: linear 16B memcpy from pre-split global buffers ----
    {
        const uint4* w1g = (const uint4*)g_w1s;
        uint4* w1smem = (uint4*)(smc + OFF_W1);
#pragma unroll
        for (int i = 0; i < 9; i++) {
            int f = tid + i * 256;
            if (f < 2176) w1smem[f] = __ldg(w1g + f);
        }
        const uint4* w2g = (const uint4*)g_w2s;
        uint4* w2smem = (uint4*)(smc + OFF_W2);
#pragma unroll
        for (int i = 0; i < 9; i++) {
            int f = tid + i * 256;
            if (f < 2112) w2smem[f] = __ldg(w2g + f);
        }
    }
    // ---- stage A (hi|lo) from g_agg; re-zero g_agg ----
#pragma unroll
    for (int i = 0; i < 8; i++) {
        int f = tid + i * 256;
        int r = f >> 4, c4 = f & 15;
        int n = node0 + r;
        float4 v = make_float4(0.f, 0.f, 0.f, 0.f);
        if (n < N) {
            v = __ldg(((const float4*)g_agg) + (size_t)n * 16 + c4);
            ((float4*)g_agg)[(size_t)n * 16 + c4] = make_float4(0.f, 0.f, 0.f, 0.f);
        }
        int k = c4 * 4;
        st_hilo2(sb + OFF_A, AS, r, k,     64, v.x, v.y);
        st_hilo2(sb + OFF_A, AS, r, k + 2, 64, v.z, v.w);
    }
    __syncthreads();

    // Fragment lane offsets (PTX m16n8k16 canonical mappings)
    int rA = (lane & 7) + ((lane >> 3) & 1) * 8;
    int cA = (lane >> 4) * 8;
    int rB = (lane & 7) + (lane >> 4) * 8;
    int cB = ((lane >> 3) & 1) * 8;
    int mw = wid & 3;
    int jw = wid >> 2;
    int m0 = mw * 32;
    int g = lane >> 2;
    int cpair = (lane & 3) * 2;

    // ---------------- GEMM1: D1 = Ahi·Whi + Ahi·Wlo + Alo·Whi ----------------
    float acc[2][8][4];
#pragma unroll
    for (int t = 0; t < 2; t++)
#pragma unroll
        for (int q = 0; q < 8; q++)
#pragma unroll
            for (int p = 0; p < 4; p++) acc[t][q][p] = 0.f;

    int j0 = jw * 64;
#pragma unroll 4
    for (int s = 0; s < 12; s++) {
        int ka = ((s & 3) << 4) + ((s >= 8) ? 64 : 0);
        int kb = ((s & 3) << 4) + ((s >= 4 && s < 8) ? 64 : 0);
        uint32_t a[2][4];
#pragma unroll
        for (int t = 0; t < 2; t++)
            LDMX4(a[t][0], a[t][1], a[t][2], a[t][3],
                  sb + OFF_A + (uint32_t)(((m0 + t * 16 + rA) * AS + ka + cA) * 2));
#pragma unroll
        for (int nt = 0; nt < 4; nt++) {
            uint32_t b0, b1r, b2, b3;
            LDMX4(b0, b1r, b2, b3,
                  sb + OFF_W1 + (uint32_t)(((j0 + nt * 16 + rB) * AS + kb + cB) * 2));
#pragma unroll
            for (int t = 0; t < 2; t++) {
                MMA16816(acc[t][2 * nt],     a[t][0], a[t][1], a[t][2], a[t][3], b0, b1r);
                MMA16816(acc[t][2 * nt + 1], a[t][0], a[t][1], a[t][2], a[t][3], b2, b3);
            }
        }
    }
    __syncthreads();    // Abuf/W1buf dead -> Hbuf may overwrite

    // ---- epilogue 1: +b1, relu, hi/lo split -> Hbuf ----
#pragma unroll
    for (int t = 0; t < 2; t++) {
#pragma unroll
        for (int q = 0; q < 8; q++) {
            int c0 = j0 + q * 8 + cpair;
            float bv0 = __ldg(b1 + c0), bv1 = __ldg(b1 + c0 + 1);
            float x0 = fmaxf(acc[t][q][0] + bv0, 0.f);
            float x1 = fmaxf(acc[t][q][1] + bv1, 0.f);
            float y0 = fmaxf(acc[t][q][2] + bv0, 0.f);
            float y1 = fmaxf(acc[t][q][3] + bv1, 0.f);
            st_hilo2(sb + OFF_A, HS, m0 + t * 16 + g,     c0, 128, x0, x1);
            st_hilo2(sb + OFF_A, HS, m0 + t * 16 + g + 8, c0, 128, y0, y1);
        }
    }
    __syncthreads();

    // ---------------- GEMM2: D2 = Hhi·W2hi + Hlo·W2hi + Hhi·W2lo ----------------
    float acc2[2][4][4];
#pragma unroll
    for (int t = 0; t < 2; t++)
#pragma unroll
        for (int q = 0; q < 4; q++)
#pragma unroll
            for (int p = 0; p < 4; p++) acc2[t][q][p] = 0.f;

    int j0b = jw * 32;
#pragma unroll 4
    for (int s = 0; s < 24; s++) {
        int kh = ((s & 7) << 4) + ((s >= 8 && s < 16) ? 128 : 0);
        int kw = ((s & 7) << 4) + ((s >= 16) ? 128 : 0);
        uint32_t a[2][4];
#pragma unroll
        for (int t = 0; t < 2; t++)
            LDMX4(a[t][0], a[t][1], a[t][2], a[t][3],
                  sb + OFF_A + (uint32_t)(((m0 + t * 16 + rA) * HS + kh + cA) * 2));
#pragma unroll
        for (int nt = 0; nt < 2; nt++) {
            uint32_t b0, b1r, b2, b3;
            LDMX4(b0, b1r, b2, b3,
                  sb + OFF_W2 + (uint32_t)(((j0b + nt * 16 + rB) * HS + kw + cB) * 2));
#pragma unroll
            for (int t = 0; t < 2; t++) {
                MMA16816(acc2[t][2 * nt],     a[t][0], a[t][1], a[t][2], a[t][3], b0, b1r);
                MMA16816(acc2[t][2 * nt + 1], a[t][0], a[t][1], a[t][2], a[t][3], b2, b3);
            }
        }
    }

    // ---- epilogue 2: +b2 -> out ----
#pragma unroll
    for (int t = 0; t < 2; t++) {
        int n0r = node0 + m0 + t * 16 + g;
        int n1r = n0r + 8;
#pragma unroll
        for (int q = 0; q < 4; q++) {
            int c0 = j0b + q * 8 + cpair;
            float bv0 = __ldg(b2 + c0), bv1 = __ldg(b2 + c0 + 1);
            if (n0r < N)
                *(float2*)(out + (size_t)n0r * 64 + c0) =
                    make_float2(acc2[t][q][0] + bv0, acc2[t][q][1] + bv1);
            if (n1r < N)
                *(float2*)(out + (size_t)n1r * 64 + c0) =
                    make_float2(acc2[t][q][2] + bv0, acc2[t][q][3] + bv1);
        }
    }
}

// ---------------------------------------------------------------------------
// Launch: scatter (+ embedded weight prep) -> HMMA MLP
// ---------------------------------------------------------------------------
extern "C" void kernel_launch(void* const* d_in, const int* in_sizes, int n_in,
                              void* d_out, int out_size) {
    const float* node_feat = (const float*)d_in[0];
    const float* edge_feat = (const float*)d_in[1];
    const int*   ei        = (const int*)d_in[2];
    const float* W1        = (const float*)d_in[3];
    const float* b1        = (const float*)d_in[4];
    const float* W2        = (const float*)d_in[5];
    const float* b2        = (const float*)d_in[6];
    float* out = (float*)d_out;

    int N = in_sizes[0] / 64;   // 100000
    int E = in_sizes[2] / 2;    // 1200000

    cudaFuncSetAttribute(mlp_mma_kernel, cudaFuncAttributeMaxDynamicSharedMemorySize,
                         SMEM_TOTAL);

    scatter_kernel<<<(E * 16 + 255) / 256, 256>>>(node_feat, edge_feat, ei, E, W1, W2);
    mlp_mma_kernel<<<(N + 127) / 128, MLP_THREADS, SMEM_TOTAL>>>(b1, b2, out, N);
}

// round 17
// speedup vs baseline: 1.1666x; 1.0180x over previous
#include <cuda_runtime.h>
#include <cuda_bf16.h>
#include <cstdint>

#define NN 100000
#define EE 1200000

// Scratch: aggregated messages per node [N, 64]; zero at entry, MLP re-zeroes.
__device__ float g_agg[NN * 64];
// Pre-transposed hi/lo-split weights in smem-tile layout (filled per launch
// by the first 8 blocks of scatter_kernel).
__device__ __nv_bfloat16 g_w1s[128 * 136];   // [j][k] hi @k, lo @k+64
__device__ __nv_bfloat16 g_w2s[64 * 264];    // [j][k] hi @k, lo @k+128

// ---------------------------------------------------------------------------
// Helpers
// ---------------------------------------------------------------------------
__device__ __forceinline__ uint32_t smem_u32(const void* p) {
    uint32_t a;
    asm("{ .reg .u64 t; cvta.to.shared.u64 t, %1; cvt.u32.u64 %0, t; }"
        : "=r"(a) : "l"(p));
    return a;
}

#define LDMX4(d0, d1, d2, d3, addr) \
    asm volatile("ldmatrix.sync.aligned.m8n8.x4.shared.b16 {%0,%1,%2,%3}, [%4];" \
                 : "=r"(d0), "=r"(d1), "=r"(d2), "=r"(d3) : "r"(addr))

#define MMA16816(c, a0, a1, a2, a3, b0, b1) \
    asm volatile("mma.sync.aligned.m16n8k16.row.col.f32.bf16.bf16.f32 " \
                 "{%0,%1,%2,%3}, {%4,%5,%6,%7}, {%8,%9}, {%0,%1,%2,%3};" \
                 : "+f"((c)[0]), "+f"((c)[1]), "+f"((c)[2]), "+f"((c)[3]) \
                 : "r"(a0), "r"(a1), "r"(a2), "r"(a3), "r"(b0), "r"(b1))

// hi/lo split store into shared memory (used for A and H staging)
__device__ __forceinline__ void st_hilo2(uint32_t base, int stride, int row,
                                         int k, int lo_off, float x0, float x1) {
    __nv_bfloat16 h0 = __float2bfloat16(x0), h1 = __float2bfloat16(x1);
    __nv_bfloat16 g0 = __float2bfloat16(x0 - __bfloat162float(h0));
    __nv_bfloat16 g1 = __float2bfloat16(x1 - __bfloat162float(h1));
    uint32_t hw = (uint32_t)__bfloat16_as_ushort(h0) |
                  ((uint32_t)__bfloat16_as_ushort(h1) << 16);
    uint32_t lw = (uint32_t)__bfloat16_as_ushort(g0) |
                  ((uint32_t)__bfloat16_as_ushort(g1) << 16);
    uint32_t a0 = base + (uint32_t)((row * stride + k) * 2);
    uint32_t a1 = base + (uint32_t)((row * stride + k + lo_off) * 2);
    asm volatile("st.shared.b32 [%0], %1;" :: "r"(a0), "r"(hw));
    asm volatile("st.shared.b32 [%0], %1;" :: "r"(a1), "r"(lw));
}

// hi/lo split store into a global bf16 buffer (prep path)
__device__ __forceinline__ void g_hilo(__nv_bfloat16* base, int stride, int row,
                                       int k, int lo_off, float x0, float x1) {
    __nv_bfloat16 h0 = __float2bfloat16(x0), h1 = __float2bfloat16(x1);
    base[row * stride + k]     = h0;
    base[row * stride + k + 1] = h1;
    base[row * stride + k + lo_off]     = __float2bfloat16(x0 - __bfloat162float(h0));
    base[row * stride + k + lo_off + 1] = __float2bfloat16(x1 - __bfloat162float(h1));
}

// ---------------------------------------------------------------------------
// Kernel 1: scatter-add (16 threads/edge, RED.v4). Blocks 0-7 additionally
// perform the per-launch weight transpose + hi/lo split (hidden under the
// scatter's memory-bound runtime).
// ---------------------------------------------------------------------------
__global__ void scatter_kernel(const float* __restrict__ node_feat,
                               const float* __restrict__ edge_feat,
                               const int* __restrict__ ei, int E,
                               const float* __restrict__ W1,
                               const float* __restrict__ W2) {
    if (blockIdx.x < 8) {
        int q = blockIdx.x * 256 + threadIdx.x;    // 0..2047
        if (q < 1024) {
            int kp = q & 31, j4 = q >> 5;
            int k0 = kp * 2;
            float4 wa = __ldg(((const float4*)W1) + k0 * 32 + j4);
            float4 wb = __ldg(((const float4*)W1) + (k0 + 1) * 32 + j4);
            int j = j4 * 4;
            g_hilo(g_w1s, 136, j + 0, k0, 64, wa.x, wb.x);
            g_hilo(g_w1s, 136, j + 1, k0, 64, wa.y, wb.y);
            g_hilo(g_w1s, 136, j + 2, k0, 64, wa.z, wb.z);
            g_hilo(g_w1s, 136, j + 3, k0, 64, wa.w, wb.w);
        } else {
            int q2 = q - 1024;
            int kp = q2 & 63, j4 = q2 >> 6;
            int k0 = kp * 2;
            float4 wa = __ldg(((const float4*)W2) + k0 * 16 + j4);
            float4 wb = __ldg(((const float4*)W2) + (k0 + 1) * 16 + j4);
            int j = j4 * 4;
            g_hilo(g_w2s, 264, j + 0, k0, 128, wa.x, wb.x);
            g_hilo(g_w2s, 264, j + 1, k0, 128, wa.y, wb.y);
            g_hilo(g_w2s, 264, j + 2, k0, 128, wa.z, wb.z);
            g_hilo(g_w2s, 264, j + 3, k0, 128, wa.w, wb.w);
        }
    }
    int gid = blockIdx.x * blockDim.x + threadIdx.x;
    if (gid >= E * 16) return;
    int e = gid >> 4;
    int c = gid & 15;
    int s = __ldg(ei + e);
    int d = __ldg(ei + E + e);
    float4 nf = __ldg(((const float4*)node_feat) + s * 16 + c);
    float4 ef = __ldg(((const float4*)edge_feat) + (size_t)e * 16 + c);
    float4 m = make_float4(nf.x + ef.x, nf.y + ef.y, nf.z + ef.z, nf.w + ef.w);
    float* p = g_agg + (size_t)d * 64 + (c << 2);
    asm volatile("red.global.add.v4.f32 [%0], {%1, %2, %3, %4};"
                 :: "l"(p), "f"(m.x), "f"(m.y), "f"(m.z), "f"(m.w)
                 : "memory");
}

// ---------------------------------------------------------------------------
// Kernel 2: HMMA MLP (round-15 proven structure; W2 staging deferred past
// GEMM1 so its LDG latency hides under MMA work instead of the first barrier).
// 128 nodes/block, 256 threads (4m x 2j warp grid), 2 blocks/SM.
//   Abuf  [128m][136] bf16: Ahi | Alo                 @ 0      (34816B)
//   W1buf [128j][136] bf16 (memcpy from g_w1s)        @ 34816  (34816B)
//   Hbuf  [128m][264] bf16: Hhi | Hlo                 @ 0      (aliases A+W1)
//   W2buf [64j][264]  bf16 (memcpy from g_w2s)        @ 69632  (33792B)
// Warp tiles: GEMM1 32m x 64j; GEMM2 32m x 32j.
// ---------------------------------------------------------------------------
#define MLP_THREADS 256
#define AS 136
#define HS 264
#define OFF_A  0u
#define OFF_W1 34816u
#define OFF_W2 69632u
#define SMEM_TOTAL 103424

__global__ void __launch_bounds__(MLP_THREADS, 2) mlp_mma_kernel(
    const float* __restrict__ b1, const float* __restrict__ b2,
    float* __restrict__ out, int N) {
    extern __shared__ char smc[];
    uint32_t sb = smem_u32(smc);
    int tid = threadIdx.x;
    int lane = tid & 31;
    int wid = tid >> 5;
    int node0 = blockIdx.x * 128;

    // ---- stage W1 (needed by GEMM1): linear 16B memcpy ----
    {
        const uint4* w1g = (const uint4*)g_w1s;
        uint4* w1smem = (uint4*)(smc + OFF_W1);
#pragma unroll
        for (int i = 0; i < 9; i++) {
            int f = tid + i * 256;
            if (f < 2176) w1smem[f] = __ldg(w1g + f);
        }
    }
    // ---- stage A (hi|lo) from g_agg; re-zero g_agg ----
#pragma unroll
    for (int i = 0; i < 8; i++) {
        int f = tid + i * 256;
        int r = f >> 4, c4 = f & 15;
        int n = node0 + r;
        float4 v = make_float4(0.f, 0.f, 0.f, 0.f);
        if (n < N) {
            v = __ldg(((const float4*)g_agg) + (size_t)n * 16 + c4);
            ((float4*)g_agg)[(size_t)n * 16 + c4] = make_float4(0.f, 0.f, 0.f, 0.f);
        }
        int k = c4 * 4;
        st_hilo2(sb + OFF_A, AS, r, k,     64, v.x, v.y);
        st_hilo2(sb + OFF_A, AS, r, k + 2, 64, v.z, v.w);
    }
    __syncthreads();

    // Fragment lane offsets (PTX m16n8k16 canonical mappings)
    int rA = (lane & 7) + ((lane >> 3) & 1) * 8;
    int cA = (lane >> 4) * 8;
    int rB = (lane & 7) + (lane >> 4) * 8;
    int cB = ((lane >> 3) & 1) * 8;
    int mw = wid & 3;
    int jw = wid >> 2;
    int m0 = mw * 32;
    int g = lane >> 2;
    int cpair = (lane & 3) * 2;

    // ---------------- GEMM1: D1 = Ahi·Whi + Ahi·Wlo + Alo·Whi ----------------
    float acc[2][8][4];
#pragma unroll
    for (int t = 0; t < 2; t++)
#pragma unroll
        for (int q = 0; q < 8; q++)
#pragma unroll
            for (int p = 0; p < 4; p++) acc[t][q][p] = 0.f;

    int j0 = jw * 64;
#pragma unroll 4
    for (int s = 0; s < 12; s++) {
        int ka = ((s & 3) << 4) + ((s >= 8) ? 64 : 0);
        int kb = ((s & 3) << 4) + ((s >= 4 && s < 8) ? 64 : 0);
        uint32_t a[2][4];
#pragma unroll
        for (int t = 0; t < 2; t++)
            LDMX4(a[t][0], a[t][1], a[t][2], a[t][3],
                  sb + OFF_A + (uint32_t)(((m0 + t * 16 + rA) * AS + ka + cA) * 2));
#pragma unroll
        for (int nt = 0; nt < 4; nt++) {
            uint32_t b0, b1r, b2r, b3;
            LDMX4(b0, b1r, b2r, b3,
                  sb + OFF_W1 + (uint32_t)(((j0 + nt * 16 + rB) * AS + kb + cB) * 2));
#pragma unroll
            for (int t = 0; t < 2; t++) {
                MMA16816(acc[t][2 * nt],     a[t][0], a[t][1], a[t][2], a[t][3], b0, b1r);
                MMA16816(acc[t][2 * nt + 1], a[t][0], a[t][1], a[t][2], a[t][3], b2r, b3);
            }
        }
    }

    // ---- stage W2 (needed only by GEMM2; W2buf region disjoint from Hbuf).
    // Issued here so the LDG latency hides under GEMM1's tail + epilogue-1;
    // visibility for GEMM2 is guaranteed by the barrier after epilogue 1. ----
    {
        const uint4* w2g = (const uint4*)g_w2s;
        uint4* w2smem = (uint4*)(smc + OFF_W2);
#pragma unroll
        for (int i = 0; i < 9; i++) {
            int f = tid + i * 256;
            if (f < 2112) w2smem[f] = __ldg(w2g + f);
        }
    }
    __syncthreads();    // Abuf/W1buf dead -> Hbuf may overwrite

    // ---- epilogue 1: +b1, relu, hi/lo split -> Hbuf ----
#pragma unroll
    for (int t = 0; t < 2; t++) {
#pragma unroll
        for (int q = 0; q < 8; q++) {
            int c0 = j0 + q * 8 + cpair;
            float bv0 = __ldg(b1 + c0), bv1 = __ldg(b1 + c0 + 1);
            float x0 = fmaxf(acc[t][q][0] + bv0, 0.f);
            float x1 = fmaxf(acc[t][q][1] + bv1, 0.f);
            float y0 = fmaxf(acc[t][q][2] + bv0, 0.f);
            float y1 = fmaxf(acc[t][q][3] + bv1, 0.f);
            st_hilo2(sb + OFF_A, HS, m0 + t * 16 + g,     c0, 128, x0, x1);
            st_hilo2(sb + OFF_A, HS, m0 + t * 16 + g + 8, c0, 128, y0, y1);
        }
    }
    __syncthreads();

    // ---------------- GEMM2: D2 = Hhi·W2hi + Hlo·W2hi + Hhi·W2lo ----------------
    float acc2[2][4][4];
#pragma unroll
    for (int t = 0; t < 2; t++)
#pragma unroll
        for (int q = 0; q < 4; q++)
#pragma unroll
            for (int p = 0; p < 4; p++) acc2[t][q][p] = 0.f;

    int j0b = jw * 32;
#pragma unroll 4
    for (int s = 0; s < 24; s++) {
        int kh = ((s & 7) << 4) + ((s >= 8 && s < 16) ? 128 : 0);
        int kw = ((s & 7) << 4) + ((s >= 16) ? 128 : 0);
        uint32_t a[2][4];
#pragma unroll
        for (int t = 0; t < 2; t++)
            LDMX4(a[t][0], a[t][1], a[t][2], a[t][3],
                  sb + OFF_A + (uint32_t)(((m0 + t * 16 + rA) * HS + kh + cA) * 2));
#pragma unroll
        for (int nt = 0; nt < 2; nt++) {
            uint32_t b0, b1r, b2r, b3;
            LDMX4(b0, b1r, b2r, b3,
                  sb + OFF_W2 + (uint32_t)(((j0b + nt * 16 + rB) * HS + kw + cB) * 2));
#pragma unroll
            for (int t = 0; t < 2; t++) {
                MMA16816(acc2[t][2 * nt],     a[t][0], a[t][1], a[t][2], a[t][3], b0, b1r);
                MMA16816(acc2[t][2 * nt + 1], a[t][0], a[t][1], a[t][2], a[t][3], b2r, b3);
            }
        }
    }

    // ---- epilogue 2: +b2 -> out ----
#pragma unroll
    for (int t = 0; t < 2; t++) {
        int n0r = node0 + m0 + t * 16 + g;
        int n1r = n0r + 8;
#pragma unroll
        for (int q = 0; q < 4; q++) {
            int c0 = j0b + q * 8 + cpair;
            float bv0 = __ldg(b2 + c0), bv1 = __ldg(b2 + c0 + 1);
            if (n0r < N)
                *(float2*)(out + (size_t)n0r * 64 + c0) =
                    make_float2(acc2[t][q][0] + bv0, acc2[t][q][1] + bv1);
            if (n1r < N)
                *(float2*)(out + (size_t)n1r * 64 + c0) =
                    make_float2(acc2[t][q][2] + bv0, acc2[t][q][3] + bv1);
        }
    }
}

// ---------------------------------------------------------------------------
// Launch: scatter (+ embedded weight prep) -> HMMA MLP
// ---------------------------------------------------------------------------
extern "C" void kernel_launch(void* const* d_in, const int* in_sizes, int n_in,
                              void* d_out, int out_size) {
    const float* node_feat = (const float*)d_in[0];
    const float* edge_feat = (const float*)d_in[1];
    const int*   ei        = (const int*)d_in[2];
    const float* W1        = (const float*)d_in[3];
    const float* b1        = (const float*)d_in[4];
    const float* W2        = (const float*)d_in[5];
    const float* b2        = (const float*)d_in[6];
    float* out = (float*)d_out;

    int N = in_sizes[0] / 64;   // 100000
    int E = in_sizes[2] / 2;    // 1200000

    cudaFuncSetAttribute(mlp_mma_kernel, cudaFuncAttributeMaxDynamicSharedMemorySize,
                         SMEM_TOTAL);

    scatter_kernel<<<(E * 16 + 255) / 256, 256>>>(node_feat, edge_feat, ei, E, W1, W2);
    mlp_mma_kernel<<<(N + 127) / 128, MLP_THREADS, SMEM_TOTAL>>>(b1, b2, out, N);
}